// round 1
// baseline (speedup 1.0000x reference)
#include <cuda_runtime.h>

#define BB 128
#define TT 256
#define KDIM 50
#define KK 2500          // K*K
#define START_TAG 48
#define END_TAG 49
#define NTHREADS 256

__device__ float g_apart[BB];   // alpha[END_TAG] per sequence (natural log)
__device__ float g_gpart[BB];   // gold partial per sequence

__device__ __forceinline__ void cp16(void* dst_smem, const void* src) {
    unsigned s = (unsigned)__cvta_generic_to_shared(dst_smem);
    asm volatile("cp.async.cg.shared.global [%0], [%1], 16;\n" :: "r"(s), "l"(src));
}
__device__ __forceinline__ void cp_commit() {
    asm volatile("cp.async.commit_group;\n");
}
template <int N>
__device__ __forceinline__ void cp_wait() {
    asm volatile("cp.async.wait_group %0;\n" :: "n"(N));
}

__global__ __launch_bounds__(NTHREADS, 1)
void viterbi_forward_kernel(const float* __restrict__ scores,
                            const int* __restrict__ targets,
                            const int* __restrict__ lengths) {
    __shared__ __align__(16) float buf[3 * KK];   // triple-buffered 50x50 tiles
    __shared__ float a2[64];                      // alpha * log2(e)
    __shared__ float red[4 * 64];                 // per-group max
    __shared__ float red2[4 * 64];                // per-group exp-sum
    __shared__ int tg[TT];

    const int b   = blockIdx.x;
    const int tid = threadIdx.x;
    const int g   = tid >> 6;     // j-group 0..3
    const int k   = tid & 63;     // column lane (valid if < 50)
    const int len = lengths[b];
    const float* base = scores + (size_t)b * TT * KK;
    const float L = 1.4426950408889634f;  // log2(e)

    tg[tid] = targets[b * TT + tid];

    auto issue = [&](int t) {
        const float4* src = (const float4*)(base + (size_t)t * KK);
        float* d = buf + (t % 3) * KK;
        for (int i = tid; i < 625; i += NTHREADS)   // 625 float4 = 10000 B
            cp16((float4*)d + i, src + i);
        cp_commit();
    };

    issue(0);
    if (len > 1) issue(1);
    if (len > 2) issue(2);

    float gold = 0.f;

    for (int t = 0; t < len; ++t) {
        int rem = len - 1 - t;
        if (rem >= 2)      cp_wait<2>();
        else if (rem == 1) cp_wait<1>();
        else               cp_wait<0>();
        __syncthreads();                         // barA: tile t visible, prev alpha visible

        const float* sb = buf + (t % 3) * KK;
        if (tid == 0) gold += sb[tg[t]];         // gold gather (tile in smem)

        if (t == 0) {
            if (g == 0 && k < KDIM) a2[k] = sb[START_TAG * KDIM + k] * L;
            __syncthreads();                     // sb reads done, a2 init done
            if (t + 3 < len) issue(t + 3);
        } else {
            float v[13];
            float m  = -3.4e38f;
            float mk = -3.4e38f;
            if (k < KDIM) {
                #pragma unroll
                for (int i = 0; i < 13; ++i) {
                    int j = g + 4 * i;
                    v[i] = (j < KDIM) ? __fmaf_rn(sb[j * KDIM + k], L, a2[j]) : -3.4e38f;
                    m = fmaxf(m, v[i]);
                }
                red[(g << 6) + k] = m;
            }
            __syncthreads();                     // barB1: sb now free, red ready

            if (t + 3 < len) issue(t + 3);       // prefetch into freed buffer, overlaps exp pass

            if (k < KDIM) {
                mk = fmaxf(fmaxf(red[k], red[64 + k]),
                           fmaxf(red[128 + k], red[192 + k]));
                float s = 0.f;
                #pragma unroll
                for (int i = 0; i < 13; ++i) {
                    float e;
                    asm("ex2.approx.f32 %0, %1;" : "=f"(e) : "f"(v[i] - mk));
                    s += e;                      // ex2(-huge) flushes to 0 for inactive j
                }
                red2[(g << 6) + k] = s;
            }
            __syncthreads();                     // barB2: red2 ready

            if (g == 0 && k < KDIM) {
                float tot = red2[k] + red2[64 + k] + red2[128 + k] + red2[192 + k];
                float lg;
                asm("lg2.approx.f32 %0, %1;" : "=f"(lg) : "f"(tot));
                a2[k] = mk + lg;                 // next iter's barA orders this for readers
            }
        }
    }

    __syncthreads();
    if (tid == 0) {
        g_gpart[b] = gold;
        g_apart[b] = a2[END_TAG] * 0.6931471805599453f;  // back to natural log
    }
}

__global__ void viterbi_finalize_kernel(float* __restrict__ out) {
    int tid = threadIdx.x;   // 128 threads
    float a  = g_apart[tid];
    float gd = g_gpart[tid];
    #pragma unroll
    for (int o = 16; o > 0; o >>= 1) {
        a  += __shfl_down_sync(0xFFFFFFFFu, a, o);
        gd += __shfl_down_sync(0xFFFFFFFFu, gd, o);
    }
    __shared__ float sa[4], sg[4];
    if ((tid & 31) == 0) { sa[tid >> 5] = a; sg[tid >> 5] = gd; }
    __syncthreads();
    if (tid == 0) {
        float A = sa[0] + sa[1] + sa[2] + sa[3];
        float G = sg[0] + sg[1] + sg[2] + sg[3];
        out[0] = (A - G) / (float)BB;
    }
}

extern "C" void kernel_launch(void* const* d_in, const int* in_sizes, int n_in,
                              void* d_out, int out_size) {
    const float* scores  = (const float*)d_in[0];
    const int*   targets = (const int*)d_in[1];
    const int*   lengths = (const int*)d_in[2];
    // d_in[3] = tmap_correct (unused scalar)
    viterbi_forward_kernel<<<BB, NTHREADS>>>(scores, targets, lengths);
    viterbi_finalize_kernel<<<1, 128>>>((float*)d_out);
}

// round 2
// speedup vs baseline: 1.3173x; 1.3173x over previous
#include <cuda_runtime.h>

#define BB 128
#define TT 256
#define KDIM 50
#define KK 2500          // K*K
#define START_TAG 48
#define END_TAG 49
#define NTHREADS 256

__device__ float g_apart[BB];   // alpha[END_TAG] per sequence (natural log)
__device__ float g_gpart[BB];   // gold partial per sequence
__device__ int   g_count = 0;   // last-block-done counter (self-resetting)

__device__ __forceinline__ void cp16(void* dst_smem, const void* src) {
    unsigned s = (unsigned)__cvta_generic_to_shared(dst_smem);
    asm volatile("cp.async.cg.shared.global [%0], [%1], 16;\n" :: "r"(s), "l"(src));
}
__device__ __forceinline__ void cp_commit() {
    asm volatile("cp.async.commit_group;\n");
}
template <int N>
__device__ __forceinline__ void cp_wait() {
    asm volatile("cp.async.wait_group %0;\n" :: "n"(N));
}

__global__ __launch_bounds__(NTHREADS, 1)
void viterbi_fused_kernel(const float* __restrict__ scores,
                          const int* __restrict__ targets,
                          const int* __restrict__ lengths,
                          float* __restrict__ out) {
    __shared__ __align__(16) float buf[4 * KK];  // quad-buffered 50x50 tiles (40 KB)
    __shared__ float a2buf[64];                  // log2-domain alpha, relative to running shift
    __shared__ float red2[4 * 64];               // per-group exp sums
    __shared__ float gm[2][4];                   // per-group max of shifted alpha (double buffered)
    __shared__ int   tg[TT];
    __shared__ int   sflag;
    __shared__ float sa[8], sg[8];

    const int b   = blockIdx.x;
    const int tid = threadIdx.x;
    const int g   = tid >> 6;     // j-group 0..3
    const int k   = tid & 63;     // column lane (active if < 50)
    const int len = lengths[b];
    const float* base = scores + (size_t)b * TT * KK;
    const float L = 1.4426950408889634f;  // log2(e)

    tg[tid] = targets[b * TT + tid];

    auto issue = [&](int t) {
        const float4* src = (const float4*)(base + (size_t)t * KK);
        float* dst = buf + (t & 3) * KK;
        #pragma unroll
        for (int i = 0; i < 3; ++i) {
            int idx = tid + i * NTHREADS;
            if (idx < 625) cp16((float4*)dst + idx, src + idx);  // 625 x 16B = 10000 B
        }
        cp_commit();
    };

    issue(0);
    if (len > 1) issue(1);
    if (len > 2) issue(2);

    float gold = 0.f;
    float shiftsum = 0.f;

    // ---- t = 0: init alpha from START row ----
    {
        int rem = len - 1;
        if (rem >= 2)      cp_wait<2>();
        else if (rem == 1) cp_wait<1>();
        else               cp_wait<0>();
        __syncthreads();
        const float* sb = buf;
        if (tid == 0) gold = sb[tg[0]];
        if (g == 0 && k < KDIM) a2buf[k] = sb[START_TAG * KDIM + k] * L;
        if (3 < len) issue(3);
        __syncthreads();
        if (tid < 4) {   // one-time per-group max init (j-subset {tid + 4i})
            float m = -1e30f;
            #pragma unroll
            for (int i = 0; i < 13; ++i) {
                int j = tid + 4 * i;
                if (j < KDIM) m = fmaxf(m, a2buf[j]);
            }
            gm[0][tid] = m;
        }
        // ordered by the loop-top __syncthreads
    }

    for (int t = 1; t < len; ++t) {
        int rem = len - 1 - t;
        if (rem >= 2)      cp_wait<2>();
        else if (rem == 1) cp_wait<1>();
        else               cp_wait<0>();
        __syncthreads();                            // barA: tile t + alpha + gm visible

        const float* sb  = buf + (t & 3) * KK;
        const float* gmr = gm[(t - 1) & 1];
        float d = fmaxf(fmaxf(gmr[0], gmr[1]), fmaxf(gmr[2], gmr[3])) + 16.0f;
        shiftsum += d;

        if (t + 3 < len) issue(t + 3);              // into tile (t-1)'s drained slot
        if (tid == 0) gold += sb[tg[t]];

        if (k < KDIM) {
            float a2m[13];
            float mloc = -1e30f;
            #pragma unroll
            for (int i = 0; i < 13; ++i) {
                int j = g + 4 * i;
                a2m[i] = (j < KDIM) ? (a2buf[j] - d) : -1e30f;
                mloc = fmaxf(mloc, a2m[i]);
            }
            float s = 0.f;
            #pragma unroll
            for (int i = 0; i < 13; ++i) {
                int j  = g + 4 * i;
                int jj = (j < KDIM) ? j : 0;
                float e;
                asm("ex2.approx.f32 %0, %1;"
                    : "=f"(e) : "f"(__fmaf_rn(sb[jj * KDIM + k], L, a2m[i])));
                s += e;                              // inactive j: ex2(~-1e30) -> 0
            }
            red2[(g << 6) + k] = s;
            if (k == 0) gm[t & 1][g] = mloc;         // free shift update for step t+1
        }
        __syncthreads();                            // barB: red2 + gm ready

        if (g == 0 && k < KDIM) {
            float tot = red2[k] + red2[64 + k] + red2[128 + k] + red2[192 + k];
            float lg;
            asm("lg2.approx.f32 %0, %1;" : "=f"(lg) : "f"(tot));
            a2buf[k] = lg;                          // relative to shift_t
        }
    }

    __syncthreads();
    if (tid == 0) {
        g_gpart[b] = gold;
        g_apart[b] = (shiftsum + a2buf[END_TAG]) * 0.6931471805599453f;
        __threadfence();
        int old = atomicAdd(&g_count, 1);
        sflag = (old == BB - 1) ? 1 : 0;
    }
    __syncthreads();

    if (sflag) {                                    // last block: deterministic final reduce
        __threadfence();
        float a = 0.f, gd = 0.f;
        if (tid < BB) { a = g_apart[tid]; gd = g_gpart[tid]; }
        #pragma unroll
        for (int o = 16; o > 0; o >>= 1) {
            a  += __shfl_down_sync(0xFFFFFFFFu, a, o);
            gd += __shfl_down_sync(0xFFFFFFFFu, gd, o);
        }
        if ((tid & 31) == 0) { sa[tid >> 5] = a; sg[tid >> 5] = gd; }
        __syncthreads();
        if (tid == 0) {
            float A = sa[0] + sa[1] + sa[2] + sa[3];
            float G = sg[0] + sg[1] + sg[2] + sg[3];
            out[0] = (A - G) / (float)BB;
            atomicExch(&g_count, 0);                // reset for next graph replay
        }
    }
}

extern "C" void kernel_launch(void* const* d_in, const int* in_sizes, int n_in,
                              void* d_out, int out_size) {
    const float* scores  = (const float*)d_in[0];
    const int*   targets = (const int*)d_in[1];
    const int*   lengths = (const int*)d_in[2];
    // d_in[3] = tmap_correct (unused scalar)
    viterbi_fused_kernel<<<BB, NTHREADS>>>(scores, targets, lengths, (float*)d_out);
}